// round 13
// baseline (speedup 1.0000x reference)
#include <cuda_runtime.h>
#include <cstdint>

// Problem constants
#define Bb    8
#define Dh    256
#define Tt    8192
#define NQ    8
#define BINS  1024

// Tiling
#define POS      64                  // t positions per CTA
#define THREADS  256
#define NCTA     ((Bb * Tt) / POS)   // 1024
#define NCHUNK   (NQ * 16)           // 128 staged codeword chunks (s,p,dk)

// Output layout (float32 concat): quantized [B,D,T], codes [NQ,B,T], bw, loss
#define Q_ELEMS   ((size_t)Bb * Dh * Tt)          // 16777216
#define C_OFF     Q_ELEMS
#define C_ELEMS   ((size_t)NQ * Bb * Tt)          // 524288
#define BW_OFF    (C_OFF + C_ELEMS)               // 17301504
#define LOSS_OFF  (BW_OFF + 1)                    // 17301505

typedef unsigned long long u64;
typedef unsigned int u32;

__device__ float g_half_cbsq[NQ * BINS];
__device__ float g_partials[NCTA];

__device__ __forceinline__ void fma2(u64 &acc, u64 a, u64 b) {
    asm("fma.rn.f32x2 %0, %1, %2, %0;" : "+l"(acc) : "l"(a), "l"(b));
}
__device__ __forceinline__ void cp8(u32 dst, const float* src) {
    asm volatile("cp.async.ca.shared.global [%0], [%1], 8;\n"
                 :: "r"(dst), "l"(src));
}
__device__ __forceinline__ void cp_commit() {
    asm volatile("cp.async.commit_group;\n" ::: "memory");
}
__device__ __forceinline__ void cp_wait0() {
    asm volatile("cp.async.wait_group 0;\n" ::: "memory");
}

// ---------------------------------------------------------------------------
// Precompute 0.5 * ||c||^2 for every codeword. One warp per codeword row.
// ---------------------------------------------------------------------------
__global__ void prep_kernel(const float* __restrict__ cb) {
    int warp = (blockIdx.x * blockDim.x + threadIdx.x) >> 5;
    int lane = threadIdx.x & 31;
    if (warp >= NQ * BINS) return;
    const float* row = cb + (size_t)warp * Dh;
    float s = 0.f;
    for (int d = lane; d < Dh; d += 32) { float v = row[d]; s += v * v; }
    #pragma unroll
    for (int o = 16; o; o >>= 1) s += __shfl_xor_sync(0xffffffffu, s, o);
    if (lane == 0) g_half_cbsq[warp] = 0.5f * s;
}

// ---------------------------------------------------------------------------
// Main fused RVQ kernel. One CTA handles 64 consecutive t positions of one b.
// Residuals live in SMEM across all 8 stages. Warp w owns positions w*8..w*8+7.
// Codeword chunks (256 rows x 64 dims) are double-buffered via cp.async with
// ONE barrier per chunk:
//   { cp.wait0 ; barrier ; stage(gc+1) ; compute(gc) }
// wait0-before-barrier publishes every warp's chunk-gc rows; the same barrier
// proves chunk gc-1 compute is done, so stage(gc+1) may overwrite its buffer.
// ---------------------------------------------------------------------------
#define CW_STRIDE 33   // float2 units per cw row (264 B, conflict-free LDS.64)

struct Smem {
    float2 res[POS][129];            // residual [pos][d/2], odd f2 row stride
    float2 cw[2][256][CW_STRIDE];    // double-buffered codeword chunks
    float  wloss[8];
};

__global__ void __launch_bounds__(THREADS, 1)
rvq_kernel(const float* __restrict__ x, const float* __restrict__ cb,
           float* __restrict__ out) {
    extern __shared__ char raw[];
    Smem& sm = *reinterpret_cast<Smem*>(raw);

    const int tid  = threadIdx.x;
    const int w    = tid >> 5;
    const int lane = tid & 31;
    const int b    = blockIdx.x >> 7;           // 128 CTAs per batch entry
    const int t0   = (blockIdx.x & 127) * POS;
    const size_t xbase = (size_t)b * Dh * Tt + t0;

    // smem u32 addresses of the two cw buffers (this warp's 32-row slice)
    u32 cwb[2];
    cwb[0] = (u32)__cvta_generic_to_shared(&sm.cw[0][w * 32][0]) + lane * 8;
    cwb[1] = (u32)__cvta_generic_to_shared(&sm.cw[1][w * 32][0]) + lane * 8;

    // Load x tile into residual smem (coalesced 64-float rows per d)
    for (int i = tid; i < POS * Dh; i += THREADS) {
        int d = i >> 6, tt = i & 63;
        float v = x[xbase + (size_t)d * Tt + tt];
        reinterpret_cast<float*>(&sm.res[tt][d >> 1])[d & 1] = v;
    }
    float sqacc = 0.f;

    // Stage chunk gc (s = gc>>4, codeword block p = (gc>>2)&3, dim dk = gc&3).
    // Warp stages rows [w*32, w*32+32): one 8B cp.async per lane per row
    // (warp covers a full 256B row segment -> 2 lines per instruction).
    auto stage = [&](int gc) {
        int s2 = gc >> 4, p2 = (gc >> 2) & 3, dk2 = gc & 3;
        const float* src = cb + ((size_t)s2 * BINS + p2 * 256 + w * 32) * Dh
                              + dk2 * 64 + lane * 2;
        u32 dst = cwb[gc & 1];
        #pragma unroll
        for (int r = 0; r < 32; r++)
            cp8(dst + r * (CW_STRIDE * 8), src + (size_t)r * Dh);
        cp_commit();
    };

    stage(0);           // prologue prefetch; published at first chunk barrier

    for (int s = 0; s < NQ; s++) {
        float best[8];
        int   bidx[8];
        #pragma unroll
        for (int pi = 0; pi < 8; pi++) { best[pi] = -3.4e38f; bidx[pi] = 0; }

        for (int p = 0; p < 4; p++) {            // 256-codeword passes
            u64 acc[8][8];
            #pragma unroll
            for (int pi = 0; pi < 8; pi++)
                #pragma unroll
                for (int ci = 0; ci < 8; ci++) acc[pi][ci] = 0ull;

            for (int dk = 0; dk < 4; dk++) {     // 64-dim d chunks
                const int gc = s * 16 + p * 4 + dk;
                cp_wait0();        // my staged rows of chunk gc have landed
                __syncthreads();   // publish gc; all warps done with gc-1
                if (gc + 1 < NCHUNK) stage(gc + 1);

                const float2* cwc = sm.cw[gc & 1][0];

                #pragma unroll 2
                for (int dc = 0; dc < 32; dc++) {
                    u64 rv[8], cv[8];
                    #pragma unroll
                    for (int pi = 0; pi < 8; pi++)
                        rv[pi] = *reinterpret_cast<const u64*>(
                            &sm.res[w * 8 + pi][dk * 32 + dc]);
                    #pragma unroll
                    for (int ci = 0; ci < 8; ci++)
                        cv[ci] = *reinterpret_cast<const u64*>(
                            &cwc[(lane + 32 * ci) * CW_STRIDE + dc]);
                    #pragma unroll
                    for (int pi = 0; pi < 8; pi++)
                        #pragma unroll
                        for (int ci = 0; ci < 8; ci++)
                            fma2(acc[pi][ci], rv[pi], cv[ci]);
                }
            }

            // Fold this pass into the running best (ascending idx order ->
            // strict '>' keeps the first/lowest index on ties, like argmin).
            #pragma unroll
            for (int ci = 0; ci < 8; ci++) {
                int cidx = p * 256 + 32 * ci + lane;
                float hq = g_half_cbsq[s * BINS + cidx];
                #pragma unroll
                for (int pi = 0; pi < 8; pi++) {
                    u64 a = acc[pi][ci];
                    float lo = __uint_as_float((unsigned)(a & 0xffffffffu));
                    float hi = __uint_as_float((unsigned)(a >> 32));
                    float score = lo + hi - hq;        // = dot - 0.5||c||^2
                    if (score > best[pi]) { best[pi] = score; bidx[pi] = cidx; }
                }
            }
        }

        // Per-position cross-lane argmax reduction + residual update
        const float* cbs = cb + (size_t)s * BINS * Dh;
        #pragma unroll 1
        for (int pi = 0; pi < 8; pi++) {
            float bs = best[pi];
            int   bi = bidx[pi];
            #pragma unroll
            for (int o = 16; o; o >>= 1) {
                float s2 = __shfl_xor_sync(0xffffffffu, bs, o);
                int   i2 = __shfl_xor_sync(0xffffffffu, bi, o);
                if (s2 > bs || (s2 == bs && i2 < bi)) { bs = s2; bi = i2; }
            }
            if (lane == 0)
                out[C_OFF + (size_t)(s * Bb + b) * Tt + t0 + w * 8 + pi] =
                    (float)bi;

            // r -= c[bi]; accumulate ||r_new||^2 (coalesced 8B x 32 lanes)
            const float2* crow =
                reinterpret_cast<const float2*>(cbs + (size_t)bi * Dh);
            float2* rrow = sm.res[w * 8 + pi];
            #pragma unroll
            for (int c = 0; c < 4; c++) {
                int j = lane + 32 * c;
                float2 cv = crow[j];
                float2 r  = rrow[j];
                r.x -= cv.x; r.y -= cv.y;
                rrow[j] = r;
                sqacc += r.x * r.x + r.y * r.y;
            }
        }
        // No cross-warp sync needed: each warp reads/writes only its own
        // res rows; the chunk-loop barriers cover cw buffer reuse.
    }

    __syncthreads();
    // quantized = x - r_final (coalesced)
    for (int i = tid; i < POS * Dh; i += THREADS) {
        int d = i >> 6, tt = i & 63;
        float r = reinterpret_cast<float*>(&sm.res[tt][d >> 1])[d & 1];
        size_t gi = xbase + (size_t)d * Tt + tt;
        out[gi] = x[gi] - r;
    }

    // Deterministic per-CTA loss partial
    float sq = sqacc;
    #pragma unroll
    for (int o = 16; o; o >>= 1) sq += __shfl_xor_sync(0xffffffffu, sq, o);
    if (lane == 0) sm.wloss[w] = sq;
    __syncthreads();
    if (tid == 0) {
        float tot = 0.f;
        #pragma unroll
        for (int k = 0; k < 8; k++) tot += sm.wloss[k];
        g_partials[blockIdx.x] = tot;
    }
}

// ---------------------------------------------------------------------------
// Final reduction: commit loss + bandwidth scalar
// ---------------------------------------------------------------------------
__global__ void finalize_kernel(const int* __restrict__ sr_i,
                                float* __restrict__ out) {
    __shared__ float red[256];
    int tid = threadIdx.x;
    float s = 0.f;
    for (int i = tid; i < NCTA; i += 256) s += g_partials[i];
    red[tid] = s;
    __syncthreads();
    for (int o = 128; o; o >>= 1) {
        if (tid < o) red[tid] += red[tid + o];
        __syncthreads();
    }
    if (tid == 0) {
        float total = red[0];
        out[LOSS_OFF] = 0.25f * total / (float)((size_t)NQ * Bb * Tt * Dh);
        int iv = sr_i[0];
        float sr = (iv > 0 && iv < 1000000000) ? (float)iv
                                               : __int_as_float(iv);
        out[BW_OFF] = (float)NQ * 10.0f * sr / 1000.0f;  // log2(1024)=10
    }
}

// ---------------------------------------------------------------------------
extern "C" void kernel_launch(void* const* d_in, const int* in_sizes, int n_in,
                              void* d_out, int out_size) {
    const float* x  = (const float*)d_in[0];
    const int*   sr = (const int*)d_in[1];
    const float* cb = (const float*)d_in[2];
    float* out = (float*)d_out;

    static int smem_set = 0;
    if (!smem_set) {
        cudaFuncSetAttribute(rvq_kernel,
                             cudaFuncAttributeMaxDynamicSharedMemorySize,
                             (int)sizeof(Smem));
        smem_set = 1;
    }

    prep_kernel<<<(NQ * BINS * 32 + THREADS - 1) / THREADS, THREADS>>>(cb);
    rvq_kernel<<<NCTA, THREADS, sizeof(Smem)>>>(x, cb, out);
    finalize_kernel<<<1, 256>>>(sr, out);
}

// round 14
// speedup vs baseline: 1.2729x; 1.2729x over previous
#include <cuda_runtime.h>
#include <cstdint>

// Problem constants
#define Bb    8
#define Dh    256
#define Tt    8192
#define NQ    8
#define BINS  1024

// Tiling
#define POS      64                  // t positions per CTA
#define THREADS  256
#define NCTA     ((Bb * Tt) / POS)   // 1024
#define NCHUNK   (NQ * 16)           // 128 staged codeword chunks (s,p,dk)

// Output layout (float32 concat): quantized [B,D,T], codes [NQ,B,T], bw, loss
#define Q_ELEMS   ((size_t)Bb * Dh * Tt)          // 16777216
#define C_OFF     Q_ELEMS
#define C_ELEMS   ((size_t)NQ * Bb * Tt)          // 524288
#define BW_OFF    (C_OFF + C_ELEMS)               // 17301504
#define LOSS_OFF  (BW_OFF + 1)                    // 17301505

typedef unsigned long long u64;
typedef unsigned int u32;

__device__ float g_half_cbsq[NQ * BINS];
__device__ float g_partials[NCTA];

__device__ __forceinline__ void fma2(u64 &acc, u64 a, u64 b) {
    asm("fma.rn.f32x2 %0, %1, %2, %0;" : "+l"(acc) : "l"(a), "l"(b));
}
__device__ __forceinline__ void cp8(u32 dst, const float* src) {
    asm volatile("cp.async.ca.shared.global [%0], [%1], 8;\n"
                 :: "r"(dst), "l"(src));
}
__device__ __forceinline__ void cp_commit() {
    asm volatile("cp.async.commit_group;\n" ::: "memory");
}
__device__ __forceinline__ void cp_wait0() {
    asm volatile("cp.async.wait_group 0;\n" ::: "memory");
}

// ---------------------------------------------------------------------------
// Precompute 0.5 * ||c||^2 for every codeword. One warp per codeword row.
// ---------------------------------------------------------------------------
__global__ void prep_kernel(const float* __restrict__ cb) {
    int warp = (blockIdx.x * blockDim.x + threadIdx.x) >> 5;
    int lane = threadIdx.x & 31;
    if (warp >= NQ * BINS) return;
    const float* row = cb + (size_t)warp * Dh;
    float s = 0.f;
    for (int d = lane; d < Dh; d += 32) { float v = row[d]; s += v * v; }
    #pragma unroll
    for (int o = 16; o; o >>= 1) s += __shfl_xor_sync(0xffffffffu, s, o);
    if (lane == 0) g_half_cbsq[warp] = 0.5f * s;
}

// ---------------------------------------------------------------------------
// Main fused RVQ kernel. One CTA handles 64 consecutive t positions of one b.
// Residuals live in SMEM across all 8 stages. Warp w owns positions w*8..w*8+7.
// Codeword chunks (256 rows x 64 dims) are double-buffered via cp.async with
// ONE barrier per chunk:
//   { cp.wait0 ; barrier ; stage(gc+1) ; compute(gc) }
// wait0-before-barrier publishes every warp's chunk-gc rows; the same barrier
// proves chunk gc-1 compute is done, so stage(gc+1) may overwrite its buffer.
// Inner loop identical to the R11 best (LDS.64 -> u64, unroll 1).
// ---------------------------------------------------------------------------
#define CW_STRIDE 33   // float2 units per cw row (264 B, conflict-free LDS.64)

struct Smem {
    float2 res[POS][129];            // residual [pos][d/2], odd f2 row stride
    float2 cw[2][256][CW_STRIDE];    // double-buffered codeword chunks
    float  wloss[8];
};

__global__ void __launch_bounds__(THREADS, 1)
rvq_kernel(const float* __restrict__ x, const float* __restrict__ cb,
           float* __restrict__ out) {
    extern __shared__ char raw[];
    Smem& sm = *reinterpret_cast<Smem*>(raw);

    const int tid  = threadIdx.x;
    const int w    = tid >> 5;
    const int lane = tid & 31;
    const int b    = blockIdx.x >> 7;           // 128 CTAs per batch entry
    const int t0   = (blockIdx.x & 127) * POS;
    const size_t xbase = (size_t)b * Dh * Tt + t0;

    // smem u32 addresses of the two cw buffers (this warp's 32-row slice)
    u32 cwb[2];
    cwb[0] = (u32)__cvta_generic_to_shared(&sm.cw[0][w * 32][0]) + lane * 8;
    cwb[1] = (u32)__cvta_generic_to_shared(&sm.cw[1][w * 32][0]) + lane * 8;

    // Load x tile into residual smem (coalesced 64-float rows per d)
    for (int i = tid; i < POS * Dh; i += THREADS) {
        int d = i >> 6, tt = i & 63;
        float v = x[xbase + (size_t)d * Tt + tt];
        reinterpret_cast<float*>(&sm.res[tt][d >> 1])[d & 1] = v;
    }
    float sqacc = 0.f;

    // Stage chunk gc (s = gc>>4, codeword block p = (gc>>2)&3, dim dk = gc&3).
    // Warp stages rows [w*32, w*32+32): one 8B cp.async per lane per row
    // (warp covers a full 256B row segment -> 2 lines per instruction).
    auto stage = [&](int gc) {
        int s2 = gc >> 4, p2 = (gc >> 2) & 3, dk2 = gc & 3;
        const float* src = cb + ((size_t)s2 * BINS + p2 * 256 + w * 32) * Dh
                              + dk2 * 64 + lane * 2;
        u32 dst = cwb[gc & 1];
        #pragma unroll
        for (int r = 0; r < 32; r++)
            cp8(dst + r * (CW_STRIDE * 8), src + (size_t)r * Dh);
        cp_commit();
    };

    stage(0);           // prologue prefetch; published at first chunk barrier

    for (int s = 0; s < NQ; s++) {
        float best[8];
        int   bidx[8];
        #pragma unroll
        for (int pi = 0; pi < 8; pi++) { best[pi] = -3.4e38f; bidx[pi] = 0; }

        for (int p = 0; p < 4; p++) {            // 256-codeword passes
            u64 acc[8][8];
            #pragma unroll
            for (int pi = 0; pi < 8; pi++)
                #pragma unroll
                for (int ci = 0; ci < 8; ci++) acc[pi][ci] = 0ull;

            for (int dk = 0; dk < 4; dk++) {     // 64-dim d chunks
                const int gc = s * 16 + p * 4 + dk;
                cp_wait0();        // my staged rows of chunk gc have landed
                __syncthreads();   // publish gc; all warps done with gc-1
                if (gc + 1 < NCHUNK) stage(gc + 1);

                const float2* cwc = sm.cw[gc & 1][0];

                #pragma unroll 1
                for (int dc = 0; dc < 32; dc++) {
                    u64 rv[8], cv[8];
                    #pragma unroll
                    for (int pi = 0; pi < 8; pi++)
                        rv[pi] = *reinterpret_cast<const u64*>(
                            &sm.res[w * 8 + pi][dk * 32 + dc]);
                    #pragma unroll
                    for (int ci = 0; ci < 8; ci++)
                        cv[ci] = *reinterpret_cast<const u64*>(
                            &cwc[(lane + 32 * ci) * CW_STRIDE + dc]);
                    #pragma unroll
                    for (int pi = 0; pi < 8; pi++)
                        #pragma unroll
                        for (int ci = 0; ci < 8; ci++)
                            fma2(acc[pi][ci], rv[pi], cv[ci]);
                }
            }

            // Fold this pass into the running best (ascending idx order ->
            // strict '>' keeps the first/lowest index on ties, like argmin).
            #pragma unroll
            for (int ci = 0; ci < 8; ci++) {
                int cidx = p * 256 + 32 * ci + lane;
                float hq = g_half_cbsq[s * BINS + cidx];
                #pragma unroll
                for (int pi = 0; pi < 8; pi++) {
                    u64 a = acc[pi][ci];
                    float lo = __uint_as_float((unsigned)(a & 0xffffffffu));
                    float hi = __uint_as_float((unsigned)(a >> 32));
                    float score = lo + hi - hq;        // = dot - 0.5||c||^2
                    if (score > best[pi]) { best[pi] = score; bidx[pi] = cidx; }
                }
            }
        }

        // Per-position cross-lane argmax reduction + residual update
        const float* cbs = cb + (size_t)s * BINS * Dh;
        #pragma unroll 1
        for (int pi = 0; pi < 8; pi++) {
            float bs = best[pi];
            int   bi = bidx[pi];
            #pragma unroll
            for (int o = 16; o; o >>= 1) {
                float s2 = __shfl_xor_sync(0xffffffffu, bs, o);
                int   i2 = __shfl_xor_sync(0xffffffffu, bi, o);
                if (s2 > bs || (s2 == bs && i2 < bi)) { bs = s2; bi = i2; }
            }
            if (lane == 0)
                out[C_OFF + (size_t)(s * Bb + b) * Tt + t0 + w * 8 + pi] =
                    (float)bi;

            // r -= c[bi]; accumulate ||r_new||^2 (coalesced 8B x 32 lanes)
            const float2* crow =
                reinterpret_cast<const float2*>(cbs + (size_t)bi * Dh);
            float2* rrow = sm.res[w * 8 + pi];
            #pragma unroll
            for (int c = 0; c < 4; c++) {
                int j = lane + 32 * c;
                float2 cv = crow[j];
                float2 r  = rrow[j];
                r.x -= cv.x; r.y -= cv.y;
                rrow[j] = r;
                sqacc += r.x * r.x + r.y * r.y;
            }
        }
        // No cross-warp sync needed: each warp reads/writes only its own
        // res rows; the chunk-loop barriers cover cw buffer reuse.
    }

    __syncthreads();
    // quantized = x - r_final (coalesced)
    for (int i = tid; i < POS * Dh; i += THREADS) {
        int d = i >> 6, tt = i & 63;
        float r = reinterpret_cast<float*>(&sm.res[tt][d >> 1])[d & 1];
        size_t gi = xbase + (size_t)d * Tt + tt;
        out[gi] = x[gi] - r;
    }

    // Deterministic per-CTA loss partial
    float sq = sqacc;
    #pragma unroll
    for (int o = 16; o; o >>= 1) sq += __shfl_xor_sync(0xffffffffu, sq, o);
    if (lane == 0) sm.wloss[w] = sq;
    __syncthreads();
    if (tid == 0) {
        float tot = 0.f;
        #pragma unroll
        for (int k = 0; k < 8; k++) tot += sm.wloss[k];
        g_partials[blockIdx.x] = tot;
    }
}

// ---------------------------------------------------------------------------
// Final reduction: commit loss + bandwidth scalar
// ---------------------------------------------------------------------------
__global__ void finalize_kernel(const int* __restrict__ sr_i,
                                float* __restrict__ out) {
    __shared__ float red[256];
    int tid = threadIdx.x;
    float s = 0.f;
    for (int i = tid; i < NCTA; i += 256) s += g_partials[i];
    red[tid] = s;
    __syncthreads();
    for (int o = 128; o; o >>= 1) {
        if (tid < o) red[tid] += red[tid + o];
        __syncthreads();
    }
    if (tid == 0) {
        float total = red[0];
        out[LOSS_OFF] = 0.25f * total / (float)((size_t)NQ * Bb * Tt * Dh);
        int iv = sr_i[0];
        float sr = (iv > 0 && iv < 1000000000) ? (float)iv
                                               : __int_as_float(iv);
        out[BW_OFF] = (float)NQ * 10.0f * sr / 1000.0f;  // log2(1024)=10
    }
}

// ---------------------------------------------------------------------------
extern "C" void kernel_launch(void* const* d_in, const int* in_sizes, int n_in,
                              void* d_out, int out_size) {
    const float* x  = (const float*)d_in[0];
    const int*   sr = (const int*)d_in[1];
    const float* cb = (const float*)d_in[2];
    float* out = (float*)d_out;

    static int smem_set = 0;
    if (!smem_set) {
        cudaFuncSetAttribute(rvq_kernel,
                             cudaFuncAttributeMaxDynamicSharedMemorySize,
                             (int)sizeof(Smem));
        smem_set = 1;
    }

    prep_kernel<<<(NQ * BINS * 32 + THREADS - 1) / THREADS, THREADS>>>(cb);
    rvq_kernel<<<NCTA, THREADS, sizeof(Smem)>>>(x, cb, out);
    finalize_kernel<<<1, 256>>>(sr, out);
}